// round 7
// baseline (speedup 1.0000x reference)
#include <cuda_runtime.h>

// Davies-Bouldin index, K=100 clusters, D=64 dims, N=2M fp32 points.
//
// Pipeline (graph-capturable, allocation-free):
//   dbi_sniff: detect whether `clustering` is int32 or int64 (JAX x64-off
//              silently downcasts jnp.int64 -> int32; reading int32 as i64
//              overruns the buffer 2x -> last round's illegal access).
//   dbi_zero : clear the 100x66 accumulator + out[0]
//   dbi_pass1: one streaming pass. Each block counting-sorts a 4096-point
//              tile by cluster id in smem, then each warp reduces whole
//              clusters in registers (lane l owns dims 2l,2l+1 -> one
//              coalesced float2 row-load per point) and flushes 66 floats
//              per (tile,cluster) via global atomicAdd.
//   dbi_pass2: Ai = (0.001+Sx)/(1+n);  Si from the algebraic expansion
//              sum||x-A||^2 = S2 - 2*A.Sx + n*||A||^2  (no 2nd data pass).
//   dbi_pass3: one block per row i: max_j (Si+Sj)/||Ai-Aj||, atomicAdd /K.

#define KCLUS 100
#define DFEAT 64
#define ACCW  66            // 64 dims + sumsq + count
#define TILE  4096
#define TPB   256

__device__ float g_acc[KCLUS * ACCW];
__device__ float g_Ai[KCLUS * DFEAT];
__device__ float g_Si[KCLUS];
__device__ int   g_is64;

// View the label buffer as int32 words. If the true dtype is int64 (LE, values
// 0..99), every odd word is 0. If int32, odd words are uniform cluster ids:
// P(64 samples all zero) ~ 1e-128. Samples stay within the int32 extent (2n
// words for i64, n words for i32 -> sampling the first n words is safe either way).
__global__ void dbi_sniff(const int* __restrict__ cl32, int n) {
    int t = threadIdx.x;            // 64 threads
    int step = n / 130;             // spread samples, stay < n/2 pairs
    int hi = cl32[2 * (t * step) + 1];
    unsigned any = __ballot_sync(0xffffffffu, hi != 0);
    any |= __shfl_xor_sync(0xffffffffu, any, 32 >> 1); // no-op keeper (warp=32); ballot covers warp only
    __shared__ unsigned s_any[2];
    if ((t & 31) == 0) s_any[t >> 5] = any;
    __syncthreads();
    if (t == 0) g_is64 = ((s_any[0] | s_any[1]) == 0u) ? 1 : 0;
}

__global__ void dbi_zero(float* out) {
    int i = blockIdx.x * blockDim.x + threadIdx.x;
    if (i < KCLUS * ACCW) g_acc[i] = 0.0f;
    if (i == 0) out[0] = 0.0f;
}

__global__ __launch_bounds__(TPB) void dbi_pass1(const float* __restrict__ X,
                                                 const void* __restrict__ cl_raw,
                                                 int n) {
    __shared__ unsigned char  s_cid[TILE];
    __shared__ unsigned short s_order[TILE];
    __shared__ int s_hist[KCLUS];
    __shared__ int s_start[KCLUS + 1];
    __shared__ int s_cursor[KCLUS];

    const int base = blockIdx.x * TILE;
    const int cnt  = min(TILE, n - base);
    const int is64 = g_is64;

    for (int i = threadIdx.x; i < KCLUS; i += TPB) s_hist[i] = 0;
    __syncthreads();

    // histogram + stash cluster ids (coalesced read, dtype-branched uniformly)
    if (is64) {
        const long long* cl = (const long long*)cl_raw;
        for (int i = threadIdx.x; i < cnt; i += TPB) {
            int c = (int)cl[base + i];
            s_cid[i] = (unsigned char)c;
            atomicAdd(&s_hist[c], 1);
        }
    } else {
        const int* cl = (const int*)cl_raw;
        for (int i = threadIdx.x; i < cnt; i += TPB) {
            int c = cl[base + i];
            s_cid[i] = (unsigned char)c;
            atomicAdd(&s_hist[c], 1);
        }
    }
    __syncthreads();

    // exclusive prefix over 100 bins (serial; ~400 cyc, negligible per tile)
    if (threadIdx.x == 0) {
        int acc = 0;
        for (int c = 0; c < KCLUS; c++) {
            s_start[c]  = acc;
            s_cursor[c] = acc;
            acc += s_hist[c];
        }
        s_start[KCLUS] = acc;
    }
    __syncthreads();

    // scatter local indices into cluster-contiguous order
    for (int i = threadIdx.x; i < cnt; i += TPB) {
        int c = s_cid[i];
        int pos = atomicAdd(&s_cursor[c], 1);
        s_order[pos] = (unsigned short)i;
    }
    __syncthreads();

    // each warp reduces whole clusters in registers: lane l owns dims 2l,2l+1
    const int warp = threadIdx.x >> 5;
    const int lane = threadIdx.x & 31;
    const int lo2  = lane << 1;

    for (int c = warp; c < KCLUS; c += (TPB >> 5)) {
        const int s = s_start[c];
        const int e = s_start[c + 1];
        const int m = e - s;
        if (m == 0) continue;

        float a0 = 0.f, a1 = 0.f, sq = 0.f;
        int j = s;
        // unroll x4: 4 independent 256B row loads in flight per warp
        for (; j + 4 <= e; j += 4) {
            int i0 = s_order[j + 0];
            int i1 = s_order[j + 1];
            int i2 = s_order[j + 2];
            int i3 = s_order[j + 3];
            float2 v0 = *(const float2*)(X + (((size_t)(base + i0)) << 6) + lo2);
            float2 v1 = *(const float2*)(X + (((size_t)(base + i1)) << 6) + lo2);
            float2 v2 = *(const float2*)(X + (((size_t)(base + i2)) << 6) + lo2);
            float2 v3 = *(const float2*)(X + (((size_t)(base + i3)) << 6) + lo2);
            a0 += (v0.x + v1.x) + (v2.x + v3.x);
            a1 += (v0.y + v1.y) + (v2.y + v3.y);
            sq += (v0.x * v0.x + v0.y * v0.y) + (v1.x * v1.x + v1.y * v1.y)
                + (v2.x * v2.x + v2.y * v2.y) + (v3.x * v3.x + v3.y * v3.y);
        }
        for (; j < e; j++) {
            int i0 = s_order[j];
            float2 v0 = *(const float2*)(X + (((size_t)(base + i0)) << 6) + lo2);
            a0 += v0.x;
            a1 += v0.y;
            sq += v0.x * v0.x + v0.y * v0.y;
        }

        atomicAdd(&g_acc[c * ACCW + lo2 + 0], a0);
        atomicAdd(&g_acc[c * ACCW + lo2 + 1], a1);
        #pragma unroll
        for (int o = 16; o; o >>= 1) sq += __shfl_xor_sync(0xffffffffu, sq, o);
        if (lane == 0) {
            atomicAdd(&g_acc[c * ACCW + 64], sq);
            atomicAdd(&g_acc[c * ACCW + 65], (float)m);
        }
    }
}

__global__ void dbi_pass2() {
    int k = threadIdx.x;
    if (k >= KCLUS) return;
    float nk = g_acc[k * ACCW + 65];
    float cf = 1.0f + nk;
    float inv = 1.0f / cf;
    float dot = 0.f, nrm = 0.f;
    #pragma unroll
    for (int d = 0; d < DFEAT; d++) {
        float sx = g_acc[k * ACCW + d];
        float a = (0.001f + sx) * inv;
        g_Ai[k * DFEAT + d] = a;
        dot += a * sx;
        nrm += a * a;
    }
    float ssq = g_acc[k * ACCW + 64] - 2.0f * dot + nk * nrm;
    g_Si[k] = sqrtf((0.001f + ssq) * inv);
}

__global__ void dbi_pass3(float* out) {
    __shared__ float sAi[DFEAT];
    __shared__ float wmax[4];
    const int i = blockIdx.x;
    const int t = threadIdx.x;
    if (t < DFEAT) sAi[t] = g_Ai[i * DFEAT + t];
    __syncthreads();
    const float si = g_Si[i];
    float best = 0.f;
    for (int j = t; j < KCLUS; j += 128) {
        if (j == i) continue;
        float ss = 0.f;
        #pragma unroll
        for (int d = 0; d < DFEAT; d++) {
            float df = sAi[d] - g_Ai[j * DFEAT + d];
            ss += df * df;
        }
        best = fmaxf(best, (si + g_Si[j]) / sqrtf(ss));
    }
    #pragma unroll
    for (int o = 16; o; o >>= 1) best = fmaxf(best, __shfl_xor_sync(0xffffffffu, best, o));
    if ((t & 31) == 0) wmax[t >> 5] = best;
    __syncthreads();
    if (t == 0) {
        float b = fmaxf(fmaxf(wmax[0], wmax[1]), fmaxf(wmax[2], wmax[3]));
        atomicAdd(out, b * (1.0f / (float)KCLUS));
    }
}

extern "C" void kernel_launch(void* const* d_in, const int* in_sizes, int n_in,
                              void* d_out, int out_size) {
    const float* X  = (const float*)d_in[0];
    const void*  cl = d_in[1];
    float* out = (float*)d_out;

    int n = (n_in >= 2) ? in_sizes[1] : (in_sizes[0] / DFEAT);

    dbi_sniff<<<1, 64>>>((const int*)cl, n);
    dbi_zero<<<(KCLUS * ACCW + 255) / 256, 256>>>(out);
    int nt = (n + TILE - 1) / TILE;
    dbi_pass1<<<nt, TPB>>>(X, cl, n);
    dbi_pass2<<<1, 128>>>();
    dbi_pass3<<<KCLUS, 128>>>(out);
    (void)out_size;
}

// round 8
// speedup vs baseline: 1.3334x; 1.3334x over previous
#include <cuda_runtime.h>

// Davies-Bouldin index, K=100 clusters, D=64 dims, N=2M fp32 points.
//
// 3 launches (graph-capturable, allocation-free):
//   dbi_init : dtype-sniff labels (int32 vs int64) + zero accumulators.
//   dbi_pass1: streaming pass. Each block counting-sorts a 4096-point tile
//              by cluster id in smem (warp-parallel prefix scan), then each
//              warp reduces whole clusters in registers (lane l owns dims
//              2l,2l+1 -> one coalesced float2 row-load per point, unroll 8
//              for 2KB in flight per warp) and flushes 66 floats per
//              (tile,cluster) via global atomicAdd.
//   dbi_epi  : fused pass2+pass3. Every block recomputes all Ai/Si from
//              g_acc into smem (transposed layout, conflict-free), then
//              block i takes max_j (Si+Sj)/||Ai-Aj||, atomicAdd /K.
//              Uses sum||x-A||^2 = S2 - 2*A.Sx + n*||A||^2 (no 2nd data pass).

#define KCLUS 100
#define DFEAT 64
#define ACCW  66            // 64 dims + sumsq + count
#define TILE  4096
#define TPB   256

__device__ float g_acc[KCLUS * ACCW];
__device__ int   g_is64;

// Sniff: view labels as int32 words. int64 (LE, values 0..99) => all odd
// words are 0. int32 => odd-word slots hold uniform cluster ids;
// P(64 samples all zero) ~ 1e-128. Samples stay inside the int32 extent.
__global__ void dbi_init(const int* __restrict__ cl32, int n, float* out) {
    __shared__ int s_flag;
    if (threadIdx.x == 0) s_flag = 0;
    __syncthreads();
    if (threadIdx.x < 64) {
        int step = n / 130;
        if (cl32[2 * (threadIdx.x * step) + 1] != 0) atomicOr(&s_flag, 1);
    }
    for (int i = threadIdx.x; i < KCLUS * ACCW; i += TPB) g_acc[i] = 0.0f;
    __syncthreads();
    if (threadIdx.x == 0) { g_is64 = s_flag ? 0 : 1; out[0] = 0.0f; }
}

__global__ __launch_bounds__(TPB) void dbi_pass1(const float* __restrict__ X,
                                                 const void* __restrict__ cl_raw,
                                                 int n) {
    __shared__ unsigned char  s_cid[TILE];
    __shared__ unsigned short s_order[TILE];
    __shared__ int s_hist[KCLUS];
    __shared__ int s_start[KCLUS + 1];
    __shared__ int s_cursor[KCLUS];
    __shared__ int s_wsum[4];

    const int base = blockIdx.x * TILE;
    const int cnt  = min(TILE, n - base);
    const int t    = threadIdx.x;
    const int lane = t & 31;
    const int wid  = t >> 5;

    for (int i = t; i < KCLUS; i += TPB) s_hist[i] = 0;
    __syncthreads();

    // histogram + stash cluster ids (coalesced; dtype branch is uniform)
    if (g_is64) {
        const long long* cl = (const long long*)cl_raw;
        for (int i = t; i < cnt; i += TPB) {
            int c = (int)cl[base + i];
            s_cid[i] = (unsigned char)c;
            atomicAdd(&s_hist[c], 1);
        }
    } else {
        const int* cl = (const int*)cl_raw;
        for (int i = t; i < cnt; i += TPB) {
            int c = cl[base + i];
            s_cid[i] = (unsigned char)c;
            atomicAdd(&s_hist[c], 1);
        }
    }
    __syncthreads();

    // warp-parallel exclusive prefix scan over 100 bins (warps 0-3)
    int incl = 0;
    if (t < 128) {
        incl = (t < KCLUS) ? s_hist[t] : 0;
        #pragma unroll
        for (int o = 1; o < 32; o <<= 1) {
            int u = __shfl_up_sync(0xffffffffu, incl, o);
            if (lane >= o) incl += u;
        }
        if (lane == 31) s_wsum[wid] = incl;
    }
    __syncthreads();
    if (t == 0) {
        int a = 0;
        #pragma unroll
        for (int w = 0; w < 4; w++) { int x = s_wsum[w]; s_wsum[w] = a; a += x; }
        s_start[KCLUS] = a;
    }
    __syncthreads();
    if (t < KCLUS) {
        int excl = incl - s_hist[t] + s_wsum[wid];
        s_start[t]  = excl;
        s_cursor[t] = excl;
    }
    __syncthreads();

    // scatter local indices into cluster-contiguous order
    for (int i = t; i < cnt; i += TPB) {
        int pos = atomicAdd(&s_cursor[s_cid[i]], 1);
        s_order[pos] = (unsigned short)i;
    }
    __syncthreads();

    // each warp reduces whole clusters in registers: lane l owns dims 2l,2l+1
    const int lo2 = lane << 1;
    for (int c = wid; c < KCLUS; c += (TPB >> 5)) {
        const int s = s_start[c];
        const int e = s_start[c + 1];
        const int m = e - s;
        if (m == 0) continue;

        float a0 = 0.f, a1 = 0.f, sq = 0.f;
        int j = s;
        // unroll x8: 8 independent 256B row loads in flight per warp (2KB)
        for (; j + 8 <= e; j += 8) {
            float2 v0 = *(const float2*)(X + (((size_t)(base + s_order[j + 0])) << 6) + lo2);
            float2 v1 = *(const float2*)(X + (((size_t)(base + s_order[j + 1])) << 6) + lo2);
            float2 v2 = *(const float2*)(X + (((size_t)(base + s_order[j + 2])) << 6) + lo2);
            float2 v3 = *(const float2*)(X + (((size_t)(base + s_order[j + 3])) << 6) + lo2);
            float2 v4 = *(const float2*)(X + (((size_t)(base + s_order[j + 4])) << 6) + lo2);
            float2 v5 = *(const float2*)(X + (((size_t)(base + s_order[j + 5])) << 6) + lo2);
            float2 v6 = *(const float2*)(X + (((size_t)(base + s_order[j + 6])) << 6) + lo2);
            float2 v7 = *(const float2*)(X + (((size_t)(base + s_order[j + 7])) << 6) + lo2);
            a0 += ((v0.x + v1.x) + (v2.x + v3.x)) + ((v4.x + v5.x) + (v6.x + v7.x));
            a1 += ((v0.y + v1.y) + (v2.y + v3.y)) + ((v4.y + v5.y) + (v6.y + v7.y));
            sq += (v0.x * v0.x + v0.y * v0.y) + (v1.x * v1.x + v1.y * v1.y)
                + (v2.x * v2.x + v2.y * v2.y) + (v3.x * v3.x + v3.y * v3.y)
                + (v4.x * v4.x + v4.y * v4.y) + (v5.x * v5.x + v5.y * v5.y)
                + (v6.x * v6.x + v6.y * v6.y) + (v7.x * v7.x + v7.y * v7.y);
        }
        for (; j < e; j++) {
            float2 v0 = *(const float2*)(X + (((size_t)(base + s_order[j])) << 6) + lo2);
            a0 += v0.x;
            a1 += v0.y;
            sq += v0.x * v0.x + v0.y * v0.y;
        }

        atomicAdd(&g_acc[c * ACCW + lo2 + 0], a0);
        atomicAdd(&g_acc[c * ACCW + lo2 + 1], a1);
        #pragma unroll
        for (int o = 16; o; o >>= 1) sq += __shfl_xor_sync(0xffffffffu, sq, o);
        if (lane == 0) {
            atomicAdd(&g_acc[c * ACCW + 64], sq);
            atomicAdd(&g_acc[c * ACCW + 65], (float)m);
        }
    }
}

// Fused pass2+pass3: every block recomputes Ai/Si (26KB L2 reads, cheap),
// transposed smem layout [d*K+k] => conflict-free writes & reads.
__global__ void dbi_epi(float* out) {
    __shared__ float sA[DFEAT * KCLUS];
    __shared__ float sS[KCLUS];
    __shared__ float wmax[4];
    const int t = threadIdx.x;

    if (t < KCLUS) {
        float nk  = g_acc[t * ACCW + 65];
        float inv = 1.0f / (1.0f + nk);
        float dot = 0.f, nrm = 0.f;
        #pragma unroll
        for (int d = 0; d < DFEAT; d++) {
            float sx = g_acc[t * ACCW + d];
            float a  = (0.001f + sx) * inv;
            sA[d * KCLUS + t] = a;
            dot += a * sx;
            nrm += a * a;
        }
        float ssq = g_acc[t * ACCW + 64] - 2.0f * dot + nk * nrm;
        sS[t] = sqrtf((0.001f + ssq) * inv);
    }
    __syncthreads();

    const int i  = blockIdx.x;
    const float si = sS[i];
    float best = 0.f;
    for (int j = t; j < KCLUS; j += 128) {
        if (j == i) continue;
        float ss = 0.f;
        #pragma unroll
        for (int d = 0; d < DFEAT; d++) {
            float df = sA[d * KCLUS + i] - sA[d * KCLUS + j];
            ss += df * df;
        }
        best = fmaxf(best, (si + sS[j]) / sqrtf(ss));
    }
    #pragma unroll
    for (int o = 16; o; o >>= 1) best = fmaxf(best, __shfl_xor_sync(0xffffffffu, best, o));
    if ((t & 31) == 0) wmax[t >> 5] = best;
    __syncthreads();
    if (t == 0) {
        float b = fmaxf(fmaxf(wmax[0], wmax[1]), fmaxf(wmax[2], wmax[3]));
        atomicAdd(out, b * (1.0f / (float)KCLUS));
    }
}

extern "C" void kernel_launch(void* const* d_in, const int* in_sizes, int n_in,
                              void* d_out, int out_size) {
    const float* X  = (const float*)d_in[0];
    const void*  cl = d_in[1];
    float* out = (float*)d_out;

    int n = (n_in >= 2) ? in_sizes[1] : (in_sizes[0] / DFEAT);

    dbi_init<<<1, TPB>>>((const int*)cl, n, out);
    dbi_pass1<<<(n + TILE - 1) / TILE, TPB>>>(X, cl, n);
    dbi_epi<<<KCLUS, 128>>>(out);
    (void)out_size;
}